// round 2
// baseline (speedup 1.0000x reference)
#include <cuda_runtime.h>
#include <cstdint>
#include <cmath>

// ----------------------------------------------------------------------------
// CGRU cell, B=1024, UNITS=2048.
//   X   = inputs @ Kcat            (1024 x 12288)   Kcat virtual from rk/ik
//   HZR = h_tm1  @ [Rz|Rr]         (1024 x 8192)
//   z,r = hard_sigmoid(X[:,g]+b_g+HZR[:,g]) ; RH = r*h
//   HH  = RH @ Rh                  (1024 x 4096)
//   out = z*h + (1-z)*tanh(X[:,h]+b_h+HH)
// GEMMs in TF32 mma.sync with fp32 accumulate.
// ----------------------------------------------------------------------------

#define UNITS 2048
#define Kdim  4096
#define WLD   6144   // row stride of weight matrices (3*UNITS)

// scratch (device globals: allocation-free)
__device__ float g_X  [(size_t)1024 * 12288];
__device__ float g_HZR[(size_t)1024 * 8192];
__device__ float g_Z  [(size_t)1024 * 4096];
__device__ float g_RH [(size_t)1024 * 4096];
__device__ float g_HH [(size_t)1024 * 4096];

__device__ __forceinline__ uint32_t f2tf32(float x) {
    uint32_t r;
    asm("cvt.rna.tf32.f32 %0, %1;" : "=r"(r) : "f"(x));
    return r;
}

__device__ __forceinline__ void cp16(float* dst, const float* src) {
    uint32_t s = (uint32_t)__cvta_generic_to_shared(dst);
    asm volatile("cp.async.cg.shared.global [%0], [%1], 16;" :: "r"(s), "l"(src));
}

__device__ __forceinline__ void mma_tf32(float* c, const uint32_t* a, const uint32_t* b) {
    asm volatile(
        "mma.sync.aligned.m16n8k8.row.col.f32.tf32.tf32.f32 "
        "{%0,%1,%2,%3},{%4,%5,%6,%7},{%8,%9},{%0,%1,%2,%3};"
        : "+f"(c[0]), "+f"(c[1]), "+f"(c[2]), "+f"(c[3])
        : "r"(a[0]), "r"(a[1]), "r"(a[2]), "r"(a[3]), "r"(b[0]), "r"(b[1]));
}

#define BM 128
#define BN 128
#define BK 32
#define ALD 36     // padded A row stride (floats)
#define BLD 136    // padded B row stride (floats)
#define ASTG (BM * ALD)
#define BSTG (BK * BLD)
#define SMEM_FLOATS (2 * ASTG + 2 * BSTG)
#define SMEM_BYTES (SMEM_FLOATS * 4)

// C[m, n] = sum_k A[m, k] * Bvirt[k, n]
// Bvirt per gate g = gate_base + n/4096, nn = n % 4096:
//   nn <  2048: k<2048 -> Wr[k, g*2048+nn]          ; k>=2048 ->  Wi[k-2048, ...]
//   nn >= 2048: k<2048 -> -Wi[k, g*2048+(nn-2048)]  ; k>=2048 ->  Wr[k-2048, ...]
__global__ __launch_bounds__(256, 2) void gemm_cgru(
    const float* __restrict__ A, const float* __restrict__ Wr,
    const float* __restrict__ Wi, float* __restrict__ C,
    int N, int gate_base)
{
    extern __shared__ float sm[];
    float* AsBuf[2] = { sm, sm + ASTG };
    float* BsBuf[2] = { sm + 2 * ASTG, sm + 2 * ASTG + BSTG };

    const int tid   = threadIdx.x;
    const int nBase = blockIdx.x * BN;
    const int mBase = blockIdx.y * BM;

    const int  gate      = gate_base + (nBase >> 12);
    const int  n_in_gate = nBase & 4095;
    const bool half_n    = (n_in_gate >= UNITS);
    const int  wcol      = gate * UNITS + (n_in_gate & (UNITS - 1));

    const float* Abase = A + (size_t)mBase * Kdim;

    auto load_stage = [&](int kb, int s) {
        const int kBase = kb * BK;
        const float* Ar = Abase + kBase;
#pragma unroll
        for (int i = 0; i < 4; i++) {
            int c = tid + i * 256;
            int r = c >> 3, co = (c & 7) << 2;
            cp16(&AsBuf[s][r * ALD + co], Ar + (size_t)r * Kdim + co);
        }
        const bool half_k = (kBase >= UNITS);
        const float* W = (half_k == half_n) ? Wr : Wi;
        const float* Bsrc = W + (size_t)(kBase & (UNITS - 1)) * WLD + wcol;
#pragma unroll
        for (int i = 0; i < 4; i++) {
            int c = tid + i * 256;
            int kk = c >> 5, no = (c & 31) << 2;
            cp16(&BsBuf[s][kk * BLD + no], Bsrc + (size_t)kk * WLD + no);
        }
        asm volatile("cp.async.commit_group;");
    };

    const int wid  = tid >> 5;
    const int lane = tid & 31;
    const int wm   = (wid & 1) * 64;
    const int wn   = (wid >> 1) * 32;
    const int grp  = lane >> 2;
    const int tig  = lane & 3;

    float acc[4][4][4];
#pragma unroll
    for (int a = 0; a < 4; a++)
#pragma unroll
        for (int b = 0; b < 4; b++)
#pragma unroll
            for (int c = 0; c < 4; c++) acc[a][b][c] = 0.0f;

    const int ITERS = Kdim / BK; // 128
    load_stage(0, 0);

    for (int kb = 0; kb < ITERS; ++kb) {
        const int cur = kb & 1;
        if (kb + 1 < ITERS) {
            load_stage(kb + 1, cur ^ 1);
            asm volatile("cp.async.wait_group 1;");
        } else {
            asm volatile("cp.async.wait_group 0;");
        }
        __syncthreads();

        const float sign = (half_n && (kb < (UNITS / BK))) ? -1.0f : 1.0f;
        const float* Ap = AsBuf[cur];
        const float* Bp = BsBuf[cur];

#pragma unroll
        for (int ks = 0; ks < 4; ++ks) {
            const int k0 = ks * 8;
            uint32_t af[4][4];
#pragma unroll
            for (int tm = 0; tm < 4; ++tm) {
                const int r = wm + tm * 16 + grp;
                af[tm][0] = f2tf32(Ap[r * ALD + k0 + tig]);
                af[tm][1] = f2tf32(Ap[(r + 8) * ALD + k0 + tig]);
                af[tm][2] = f2tf32(Ap[r * ALD + k0 + tig + 4]);
                af[tm][3] = f2tf32(Ap[(r + 8) * ALD + k0 + tig + 4]);
            }
            uint32_t bfr[4][2];
#pragma unroll
            for (int tn = 0; tn < 4; ++tn) {
                const int cn = wn + tn * 8 + grp;
                bfr[tn][0] = f2tf32(sign * Bp[(k0 + tig) * BLD + cn]);
                bfr[tn][1] = f2tf32(sign * Bp[(k0 + tig + 4) * BLD + cn]);
            }
#pragma unroll
            for (int tm = 0; tm < 4; ++tm)
#pragma unroll
                for (int tn = 0; tn < 4; ++tn)
                    mma_tf32(acc[tm][tn], af[tm], bfr[tn]);
        }
        __syncthreads();
    }

    // epilogue
#pragma unroll
    for (int tm = 0; tm < 4; ++tm) {
#pragma unroll
        for (int tn = 0; tn < 4; ++tn) {
            const int m0 = mBase + wm + tm * 16 + grp;
            const int n0 = nBase + wn + tn * 8 + tig * 2;
            *(float2*)&C[(size_t)m0 * N + n0]       = make_float2(acc[tm][tn][0], acc[tm][tn][1]);
            *(float2*)&C[(size_t)(m0 + 8) * N + n0] = make_float2(acc[tm][tn][2], acc[tm][tn][3]);
        }
    }
}

__device__ __forceinline__ float hsig(float x) {
    return fminf(fmaxf(0.2f * x + 0.5f, 0.0f), 1.0f);
}

// z/r gates + r*h
__global__ void ew_zr(const float* __restrict__ X, const float* __restrict__ HZR,
                      const float* __restrict__ h, const float* __restrict__ rb,
                      const float* __restrict__ ib, float* __restrict__ Z,
                      float* __restrict__ RH)
{
    const int i = blockIdx.x * blockDim.x + threadIdx.x;  // float4 index, 1024*1024 total
    const int m = i >> 10;
    const int n = (i & 1023) << 2;

    const float4 xz = *(const float4*)&X[(size_t)m * 12288 + n];
    const float4 xr = *(const float4*)&X[(size_t)m * 12288 + 4096 + n];
    const float4 hz = *(const float4*)&HZR[(size_t)m * 8192 + n];
    const float4 hr = *(const float4*)&HZR[(size_t)m * 8192 + 4096 + n];
    const float4 hv = *(const float4*)&h[(size_t)m * 4096 + n];

    const float* bsel = (n < UNITS) ? rb : ib;
    const int bo = n & (UNITS - 1);
    const float4 bz = *(const float4*)&bsel[bo];           // gate z
    const float4 br = *(const float4*)&bsel[UNITS + bo];   // gate r

    float4 zv, rhv;
    zv.x = hsig(xz.x + bz.x + hz.x);
    zv.y = hsig(xz.y + bz.y + hz.y);
    zv.z = hsig(xz.z + bz.z + hz.z);
    zv.w = hsig(xz.w + bz.w + hz.w);
    rhv.x = hsig(xr.x + br.x + hr.x) * hv.x;
    rhv.y = hsig(xr.y + br.y + hr.y) * hv.y;
    rhv.z = hsig(xr.z + br.z + hr.z) * hv.z;
    rhv.w = hsig(xr.w + br.w + hr.w) * hv.w;

    *(float4*)&Z[(size_t)m * 4096 + n]  = zv;
    *(float4*)&RH[(size_t)m * 4096 + n] = rhv;
}

// final blend
__global__ void ew_out(const float* __restrict__ X, const float* __restrict__ HH,
                       const float* __restrict__ h, const float* __restrict__ rb,
                       const float* __restrict__ ib, const float* __restrict__ Z,
                       float* __restrict__ out)
{
    const int i = blockIdx.x * blockDim.x + threadIdx.x;
    const int m = i >> 10;
    const int n = (i & 1023) << 2;

    const float4 xh = *(const float4*)&X[(size_t)m * 12288 + 8192 + n];
    const float4 hhv = *(const float4*)&HH[(size_t)m * 4096 + n];
    const float4 hv  = *(const float4*)&h[(size_t)m * 4096 + n];
    const float4 zv  = *(const float4*)&Z[(size_t)m * 4096 + n];

    const float* bsel = (n < UNITS) ? rb : ib;
    const int bo = n & (UNITS - 1);
    const float4 bh = *(const float4*)&bsel[2 * UNITS + bo];  // gate h

    float4 o;
    o.x = zv.x * hv.x + (1.0f - zv.x) * tanhf(xh.x + bh.x + hhv.x);
    o.y = zv.y * hv.y + (1.0f - zv.y) * tanhf(xh.y + bh.y + hhv.y);
    o.z = zv.z * hv.z + (1.0f - zv.z) * tanhf(xh.z + bh.z + hhv.z);
    o.w = zv.w * hv.w + (1.0f - zv.w) * tanhf(xh.w + bh.w + hhv.w);

    *(float4*)&out[(size_t)m * 4096 + n] = o;
}

extern "C" void kernel_launch(void* const* d_in, const int* in_sizes, int n_in,
                              void* d_out, int out_size)
{
    const float* inputs = (const float*)d_in[0];
    const float* h_tm1  = (const float*)d_in[1];
    const float* rk     = (const float*)d_in[2];
    const float* ik     = (const float*)d_in[3];
    const float* rrk    = (const float*)d_in[4];
    const float* irk    = (const float*)d_in[5];
    const float* rb     = (const float*)d_in[6];
    const float* ib     = (const float*)d_in[7];
    float* out = (float*)d_out;

    float *pX, *pHZR, *pZ, *pRH, *pHH;
    cudaGetSymbolAddress((void**)&pX,   g_X);
    cudaGetSymbolAddress((void**)&pHZR, g_HZR);
    cudaGetSymbolAddress((void**)&pZ,   g_Z);
    cudaGetSymbolAddress((void**)&pRH,  g_RH);
    cudaGetSymbolAddress((void**)&pHH,  g_HH);

    cudaFuncSetAttribute(gemm_cgru, cudaFuncAttributeMaxDynamicSharedMemorySize, SMEM_BYTES);

    dim3 blk(256);
    // X = inputs @ Kcat  (3 gates, N=12288)
    gemm_cgru<<<dim3(96, 8), blk, SMEM_BYTES>>>(inputs, rk, ik, pX, 12288, 0);
    // HZR = h @ [Rz|Rr]  (gates z,r, N=8192)
    gemm_cgru<<<dim3(64, 8), blk, SMEM_BYTES>>>(h_tm1, rrk, irk, pHZR, 8192, 0);
    // z, r, r*h
    ew_zr<<<4096, 256>>>(pX, pHZR, h_tm1, rb, ib, pZ, pRH);
    // HH = (r*h) @ Rh    (gate h only, N=4096, gate_base=2)
    gemm_cgru<<<dim3(32, 8), blk, SMEM_BYTES>>>(pRH, rrk, irk, pHH, 4096, 2);
    // out = z*h + (1-z)*tanh(...)
    ew_out<<<4096, 256>>>(pX, pHH, h_tm1, rb, ib, pZ, out);
}